// round 3
// baseline (speedup 1.0000x reference)
#include <cuda_runtime.h>
#include <math.h>
#include <stdint.h>

// Problem-instance constants (VectorQuantizerEnt: B=32,T=512,D=512,K=2048)
#define KC   2048      // num centroids
#define DD   512       // feature dim
#define NMAX 16384     // rows (B*T)
#define EPSQ 1e-8f

// ---------------- scratch (static device globals; no runtime allocation) ----
__device__ float  g_sim[(size_t)NMAX * KC];   // similarity matrix scratch (134 MB)
__device__ float  g_div[KC];                  // sum over rows of scores (diversity * N)
__device__ float  g_cnt[KC];                  // cluster counts
__device__ int    g_idx[NMAX];                // argmax index per row
__device__ double g_hsum;                     // sum over rows of sum_k p*log2(p+eps)
__device__ float  g_loss;                     // final scalar loss

// ---------------- reductions ------------------------------------------------
__device__ __forceinline__ float blockSum(float v) {
    __shared__ float s[8];
    int t = threadIdx.x, w = t >> 5, l = t & 31;
#pragma unroll
    for (int o = 16; o; o >>= 1) v += __shfl_xor_sync(0xffffffffu, v, o);
    if (l == 0) s[w] = v;
    __syncthreads();
    if (w == 0) {
        float x = (l < 8) ? s[l] : 0.0f;
#pragma unroll
        for (int o = 4; o; o >>= 1) x += __shfl_xor_sync(0xffffffffu, x, o);
        if (l == 0) s[0] = x;
    }
    __syncthreads();
    float r = s[0];
    __syncthreads();
    return r;
}

__device__ __forceinline__ float blockMax(float v) {
    __shared__ float s[8];
    int t = threadIdx.x, w = t >> 5, l = t & 31;
#pragma unroll
    for (int o = 16; o; o >>= 1) v = fmaxf(v, __shfl_xor_sync(0xffffffffu, v, o));
    if (l == 0) s[w] = v;
    __syncthreads();
    if (w == 0) {
        float x = (l < 8) ? s[l] : -3.4e38f;
#pragma unroll
        for (int o = 4; o; o >>= 1) x = fmaxf(x, __shfl_xor_sync(0xffffffffu, x, o));
        if (l == 0) s[0] = x;
    }
    __syncthreads();
    float r = s[0];
    __syncthreads();
    return r;
}

// argmax with tie -> lowest index (matches jnp.argmax first-occurrence)
__device__ __forceinline__ void blockMaxArg(float& v, int& i) {
    __shared__ float sv[8];
    __shared__ int   si[8];
    int t = threadIdx.x, w = t >> 5, l = t & 31;
#pragma unroll
    for (int o = 16; o; o >>= 1) {
        float ov = __shfl_xor_sync(0xffffffffu, v, o);
        int   oi = __shfl_xor_sync(0xffffffffu, i, o);
        if (ov > v || (ov == v && oi < i)) { v = ov; i = oi; }
    }
    if (l == 0) { sv[w] = v; si[w] = i; }
    __syncthreads();
    if (w == 0) {
        float vv = (l < 8) ? sv[l] : -3.4e38f;
        int   ii = (l < 8) ? si[l] : 0x7fffffff;
#pragma unroll
        for (int o = 4; o; o >>= 1) {
            float ov = __shfl_xor_sync(0xffffffffu, vv, o);
            int   oi = __shfl_xor_sync(0xffffffffu, ii, o);
            if (ov > vv || (ov == vv && oi < ii)) { vv = ov; ii = oi; }
        }
        if (l == 0) { sv[0] = vv; si[0] = ii; }
    }
    __syncthreads();
    v = sv[0]; i = si[0];
    __syncthreads();
}

// ---------------- kernels ---------------------------------------------------
__global__ void init_kernel() {
    int gid = blockIdx.x * blockDim.x + threadIdx.x;
    if (gid < KC) { g_div[gid] = 0.0f; g_cnt[gid] = 0.0f; }
    if (gid == 0) g_hsum = 0.0;
}

// C[M,KC] = A[M,DD] * B[KC,DD]^T  (fp32, 128x128x8 tile, 8x8 micro)
__global__ __launch_bounds__(256, 1)
void sgemm_nt(const float* __restrict__ A, const float* __restrict__ B) {
    __shared__ float As[8][128];
    __shared__ float Bs[8][128];
    const int tid = threadIdx.x;
    const int tx = tid & 15, ty = tid >> 4;
    const int br = blockIdx.y * 128, bc = blockIdx.x * 128;
    const int lr = tid >> 1, lk = (tid & 1) * 4;
    const float* Ap = A + (size_t)(br + lr) * DD + lk;
    const float* Bp = B + (size_t)(bc + lr) * DD + lk;
    float acc[8][8];
#pragma unroll
    for (int i = 0; i < 8; i++)
#pragma unroll
        for (int j = 0; j < 8; j++) acc[i][j] = 0.0f;

    for (int k0 = 0; k0 < DD; k0 += 8) {
        float4 av = *(const float4*)(Ap + k0);
        float4 bv = *(const float4*)(Bp + k0);
        __syncthreads();
        As[lk + 0][lr] = av.x; As[lk + 1][lr] = av.y;
        As[lk + 2][lr] = av.z; As[lk + 3][lr] = av.w;
        Bs[lk + 0][lr] = bv.x; Bs[lk + 1][lr] = bv.y;
        Bs[lk + 2][lr] = bv.z; Bs[lk + 3][lr] = bv.w;
        __syncthreads();
#pragma unroll
        for (int kk = 0; kk < 8; kk++) {
            float4 a0 = *(const float4*)&As[kk][ty * 8];
            float4 a1 = *(const float4*)&As[kk][ty * 8 + 4];
            float4 b0 = *(const float4*)&Bs[kk][tx * 8];
            float4 b1 = *(const float4*)&Bs[kk][tx * 8 + 4];
            float a[8] = {a0.x, a0.y, a0.z, a0.w, a1.x, a1.y, a1.z, a1.w};
            float b[8] = {b0.x, b0.y, b0.z, b0.w, b1.x, b1.y, b1.z, b1.w};
#pragma unroll
            for (int i = 0; i < 8; i++)
#pragma unroll
                for (int j = 0; j < 8; j++)
                    acc[i][j] = fmaf(a[i], b[j], acc[i][j]);
        }
    }
#pragma unroll
    for (int i = 0; i < 8; i++) {
        float* cp = g_sim + (size_t)(br + ty * 8 + i) * KC + bc + tx * 8;
        *(float4*)(cp)     = make_float4(acc[i][0], acc[i][1], acc[i][2], acc[i][3]);
        *(float4*)(cp + 4) = make_float4(acc[i][4], acc[i][5], acc[i][6], acc[i][7]);
    }
}

// 16 rows per CTA: softmax, argmax(scores), entropy, diversity partials, counts
#define RPC 16
__global__ __launch_bounds__(256)
void row_kernel(int nrows) {
    __shared__ float divp[KC];
    int t = threadIdx.x;
    for (int i = t; i < KC; i += 256) divp[i] = 0.0f;
    __syncthreads();

    float ent_acc = 0.0f;
    int r0 = blockIdx.x * RPC;
    for (int rr = 0; rr < RPC; rr++) {
        int r = r0 + rr;
        const float* srow = g_sim + (size_t)r * KC;
        float v[8];
#pragma unroll
        for (int j = 0; j < 8; j++) v[j] = srow[t + 256 * j];

        float m = v[0];
#pragma unroll
        for (int j = 1; j < 8; j++) m = fmaxf(m, v[j]);
        m = blockMax(m);

        float e[8];
        float z = 0.0f;
#pragma unroll
        for (int j = 0; j < 8; j++) { e[j] = expf(v[j] - m); z += e[j]; }
        z = blockSum(z);

        float pbest = -1.0f;
        int   ibest = 0x7fffffff;
#pragma unroll
        for (int j = 0; j < 8; j++) {
            float p = e[j] / z;
            int col = t + 256 * j;
            divp[col] += p;
            ent_acc += p * log2f(p + EPSQ);
            if (p > pbest || (p == pbest && col < ibest)) { pbest = p; ibest = col; }
        }
        blockMaxArg(pbest, ibest);
        if (t == 0) {
            g_idx[r] = ibest;
            atomicAdd(&g_cnt[ibest], 1.0f);
        }
    }
    float es = blockSum(ent_acc);
    if (t == 0) atomicAdd(&g_hsum, (double)es);
    __syncthreads();
    for (int i = t; i < KC; i += 256) atomicAdd(&g_div[i], divp[i]);
}

__global__ __launch_bounds__(256)
void finalize_kernel(float invN) {
    int t = threadIdx.x;
    float local = 0.0f;
    for (int i = t; i < KC; i += 256) {
        float d = g_div[i] * invN;
        local += d * log2f(d + EPSQ);
    }
    float HD = blockSum(local);   // = -h_diversity
    if (t == 0) {
        float hclust = -(float)(g_hsum * (double)invN);
        g_loss = hclust + 1.0f * HD;   // h_clust - GAMMA * h_diversity, GAMMA=1
    }
}

// one warp per row: gather codebook row, center, L2-normalize, straight-through
__global__ __launch_bounds__(256)
void quant_kernel(const float* __restrict__ x, const float* __restrict__ cb,
                  float* __restrict__ oq, int nrows) {
    int w = (blockIdx.x * 256 + threadIdx.x) >> 5;
    if (w >= nrows) return;
    int l = threadIdx.x & 31;
    const float* crow = cb + (size_t)g_idx[w] * DD;
    const float* xrow = x + (size_t)w * DD;
    float4 q[4];
    float s = 0.0f;
#pragma unroll
    for (int j = 0; j < 4; j++) {
        q[j] = *(const float4*)(crow + j * 128 + l * 4);
        s += q[j].x + q[j].y + q[j].z + q[j].w;
    }
#pragma unroll
    for (int o = 16; o; o >>= 1) s += __shfl_xor_sync(0xffffffffu, s, o);
    float mean = s * (1.0f / (float)DD);
    float ss = 0.0f;
#pragma unroll
    for (int j = 0; j < 4; j++) {
        float dx = q[j].x - mean, dy = q[j].y - mean, dz = q[j].z - mean, dw = q[j].w - mean;
        ss += dx * dx + dy * dy + dz * dz + dw * dw;
    }
#pragma unroll
    for (int o = 16; o; o >>= 1) ss += __shfl_xor_sync(0xffffffffu, ss, o);
    float nrm = sqrtf(ss);
#pragma unroll
    for (int j = 0; j < 4; j++) {
        float4 xv = *(const float4*)(xrow + j * 128 + l * 4);
        float4 o4;
        o4.x = xv.x + ((q[j].x - mean) / nrm - xv.x);
        o4.y = xv.y + ((q[j].y - mean) / nrm - xv.y);
        o4.z = xv.z + ((q[j].z - mean) / nrm - xv.z);
        o4.w = xv.w + ((q[j].w - mean) / nrm - xv.w);
        *(float4*)(oq + (size_t)w * DD + j * 128 + l * 4) = o4;
    }
}

__global__ void fill_loss_kernel(float4* __restrict__ o, size_t n4) {
    float v = g_loss;
    float4 f = make_float4(v, v, v, v);
    size_t i = (size_t)blockIdx.x * blockDim.x + threadIdx.x;
    size_t stride = (size_t)gridDim.x * blockDim.x;
    for (; i < n4; i += stride) o[i] = f;
}

__global__ void misc_kernel(const float* __restrict__ cb,
                            const float* __restrict__ old_counts,
                            const int* __restrict__ train,
                            float* __restrict__ o_idx,
                            float* __restrict__ o_cb,
                            float* __restrict__ o_cnt, int nrows) {
    int gid = blockIdx.x * blockDim.x + threadIdx.x;
    if (gid < (KC * DD) / 4) ((float4*)o_cb)[gid] = ((const float4*)cb)[gid];
    if (gid < nrows) o_idx[gid] = (float)g_idx[gid];
    if (gid < KC) {
        float oldc = old_counts[gid];
        o_cnt[gid] = (*train) ? (0.99f * oldc + 0.01f * g_cnt[gid]) : oldc;
    }
}

// ---------------- launch ----------------------------------------------------
extern "C" void kernel_launch(void* const* d_in, const int* in_sizes, int n_in,
                              void* d_out, int out_size) {
    const float* inputs   = (const float*)d_in[0];
    const float* codebook = (const float*)d_in[1];
    const float* counts   = (const float*)d_in[2];
    const int*   train    = (const int*)d_in[3];

    const int nrows = in_sizes[0] / DD;     // 16384

    float* out    = (float*)d_out;
    float* o_q    = out;                                    // nrows*DD
    float* o_loss = o_q + (size_t)nrows * DD;               // nrows*KC
    float* o_idx  = o_loss + (size_t)nrows * KC;            // nrows
    float* o_cb   = o_idx + nrows;                          // KC*DD
    float* o_cnt  = o_cb + (size_t)KC * DD;                 // KC

    init_kernel<<<(KC + 255) / 256, 256>>>();

    dim3 gemm_grid(KC / 128, nrows / 128);
    sgemm_nt<<<gemm_grid, 256>>>(inputs, codebook);

    row_kernel<<<nrows / RPC, 256>>>(nrows);

    finalize_kernel<<<1, 256>>>(1.0f / (float)nrows);

    quant_kernel<<<(nrows + 7) / 8, 256>>>(inputs, codebook, o_q, nrows);

    size_t n4 = ((size_t)nrows * KC) / 4;
    fill_loss_kernel<<<2368, 256>>>((float4*)o_loss, n4);

    misc_kernel<<<(KC * DD / 4 + 255) / 256, 256>>>(codebook, counts, train,
                                                    o_idx, o_cb, o_cnt, nrows);
}

// round 11
// speedup vs baseline: 2.4253x; 2.4253x over previous
#include <cuda_runtime.h>
#include <cuda_bf16.h>
#include <math.h>
#include <stdint.h>

// Problem-instance constants (VectorQuantizerEnt: B=32,T=512,D=512,K=2048)
#define KC   2048
#define DD   512
#define NMAX 16384
#define EPSQ 1e-8f
#define MARGIN 0.01f
#define MAXCAND 16
// sum_k p*log2((p+eps)/p) ~= K*eps*log2(e)  (exact to ~3e-10 here since eps/p <= 1e-4)
#define EPS_CORR 2.9546194437325826e-5f

// ---------------- scratch (static device globals) ---------------------------
__device__ float         g_sim[(size_t)NMAX * KC];
__device__ __nv_bfloat16 g_Ah[(size_t)NMAX * DD];
__device__ __nv_bfloat16 g_Al[(size_t)NMAX * DD];
__device__ __nv_bfloat16 g_Bh[(size_t)KC * DD];
__device__ __nv_bfloat16 g_Bl[(size_t)KC * DD];
__device__ float  g_div[KC];
__device__ float  g_cnt[KC];
__device__ int    g_idx[NMAX];
__device__ int    g_cand[NMAX][MAXCAND];
__device__ int    g_ncand[NMAX];
__device__ double g_hsum;
__device__ float  g_loss;

// ---------------- small PTX helpers -----------------------------------------
static __device__ __forceinline__ uint32_t smem_u32(const void* p) {
    uint32_t a;
    asm("{ .reg .u64 t; cvta.to.shared.u64 t, %1; cvt.u32.u64 %0, t; }" : "=r"(a) : "l"(p));
    return a;
}
static __device__ __forceinline__ void ldsm_x4(uint32_t* r, uint32_t addr) {
    asm volatile("ldmatrix.sync.aligned.m8n8.x4.shared.b16 {%0,%1,%2,%3}, [%4];"
                 : "=r"(r[0]), "=r"(r[1]), "=r"(r[2]), "=r"(r[3]) : "r"(addr));
}
static __device__ __forceinline__ void mma16816(float* c, const uint32_t* a, const uint32_t* b) {
    asm volatile("mma.sync.aligned.m16n8k16.row.col.f32.bf16.bf16.f32 "
                 "{%0,%1,%2,%3}, {%4,%5,%6,%7}, {%8,%9}, {%0,%1,%2,%3};"
                 : "+f"(c[0]), "+f"(c[1]), "+f"(c[2]), "+f"(c[3])
                 : "r"(a[0]), "r"(a[1]), "r"(a[2]), "r"(a[3]), "r"(b[0]), "r"(b[1]));
}

// ---------------- reductions ------------------------------------------------
__device__ __forceinline__ float blockSum(float v) {
    __shared__ float s[8];
    int t = threadIdx.x, w = t >> 5, l = t & 31;
#pragma unroll
    for (int o = 16; o; o >>= 1) v += __shfl_xor_sync(0xffffffffu, v, o);
    if (l == 0) s[w] = v;
    __syncthreads();
    if (w == 0) {
        float x = (l < 8) ? s[l] : 0.0f;
#pragma unroll
        for (int o = 4; o; o >>= 1) x += __shfl_xor_sync(0xffffffffu, x, o);
        if (l == 0) s[0] = x;
    }
    __syncthreads();
    float r = s[0];
    __syncthreads();
    return r;
}

__device__ __forceinline__ float blockMax(float v) {
    __shared__ float s[8];
    int t = threadIdx.x, w = t >> 5, l = t & 31;
#pragma unroll
    for (int o = 16; o; o >>= 1) v = fmaxf(v, __shfl_xor_sync(0xffffffffu, v, o));
    if (l == 0) s[w] = v;
    __syncthreads();
    if (w == 0) {
        float x = (l < 8) ? s[l] : -3.4e38f;
#pragma unroll
        for (int o = 4; o; o >>= 1) x = fmaxf(x, __shfl_xor_sync(0xffffffffu, x, o));
        if (l == 0) s[0] = x;
    }
    __syncthreads();
    float r = s[0];
    __syncthreads();
    return r;
}

// ---------------- kernels ---------------------------------------------------
__global__ void init_kernel() {
    int gid = blockIdx.x * blockDim.x + threadIdx.x;
    if (gid < KC) { g_div[gid] = 0.0f; g_cnt[gid] = 0.0f; }
    if (gid == 0) g_hsum = 0.0;
}

// fp32 -> (hi, lo) bf16 split of inputs + codebook
__global__ void convert_kernel(const float4* __restrict__ A, const float4* __restrict__ B) {
    const int NA4 = NMAX * DD / 4;
    const int NB4 = KC * DD / 4;
    int i = blockIdx.x * 256 + threadIdx.x;
    const float4* src;
    __nv_bfloat162 *oh, *ol;
    int j;
    if (i < NA4) {
        src = A; j = i;
        oh = (__nv_bfloat162*)g_Ah; ol = (__nv_bfloat162*)g_Al;
    } else if (i < NA4 + NB4) {
        src = B; j = i - NA4;
        oh = (__nv_bfloat162*)g_Bh; ol = (__nv_bfloat162*)g_Bl;
    } else return;
    float4 f = src[j];
    __nv_bfloat162 h0 = __floats2bfloat162_rn(f.x, f.y);
    __nv_bfloat162 h1 = __floats2bfloat162_rn(f.z, f.w);
    oh[2 * j]     = h0;
    oh[2 * j + 1] = h1;
    ol[2 * j]     = __floats2bfloat162_rn(f.x - __bfloat162float(h0.x),
                                          f.y - __bfloat162float(h0.y));
    ol[2 * j + 1] = __floats2bfloat162_rn(f.z - __bfloat162float(h1.x),
                                          f.w - __bfloat162float(h1.y));
}

// cp.async one 128x64 bf16 chunk (16KB) for each of 4 tiles (Ah,Al,Bh,Bl)
// stage layout: [Ah:0, Al:16K, Bh:32K, Bl:48K]
static __device__ __forceinline__ void load_chunk(
    uint32_t s,
    const __nv_bfloat16* __restrict__ Ah, const __nv_bfloat16* __restrict__ Al,
    const __nv_bfloat16* __restrict__ Bh, const __nv_bfloat16* __restrict__ Bl,
    int k0, int t)
{
    const char* pAh = (const char*)(Ah + k0);
    const char* pAl = (const char*)(Al + k0);
    const char* pBh = (const char*)(Bh + k0);
    const char* pBl = (const char*)(Bl + k0);
#pragma unroll
    for (int i = 0; i < 4; i++) {
        int u = t + i * 256;           // 1024 16B units: 128 rows x 8 units
        int row = u >> 3, c16 = u & 7;
        uint32_t off = (uint32_t)row * 128u + (uint32_t)c16 * 16u;
        uint32_t sw  = off ^ ((off >> 3) & 0x70);
        size_t go = (size_t)row * (DD * 2) + c16 * 16;
        asm volatile("cp.async.cg.shared.global [%0], [%1], 16;" :: "r"(s + sw),          "l"(pAh + go));
        asm volatile("cp.async.cg.shared.global [%0], [%1], 16;" :: "r"(s + 16384u + sw), "l"(pAl + go));
        asm volatile("cp.async.cg.shared.global [%0], [%1], 16;" :: "r"(s + 32768u + sw), "l"(pBh + go));
        asm volatile("cp.async.cg.shared.global [%0], [%1], 16;" :: "r"(s + 49152u + sw), "l"(pBl + go));
    }
}

// C = Ah*Bh^T + Ah*Bl^T + Al*Bh^T via mma.sync m16n8k16 (fp32 accum) — fp32-accurate.
// 128x128 tile, BK=64, double-buffered cp.async, 8 warps (4m x 2n), warp=32x64.
__global__ __launch_bounds__(256) void mm_kernel() {
    extern __shared__ char dyn[];
    uint32_t raw  = smem_u32(dyn);
    uint32_t base = (raw + 1023u) & ~1023u;
    int t = threadIdx.x, wid = t >> 5, lane = t & 31;
    int bc = blockIdx.x * 128, br = blockIdx.y * 128;
    int wm = (wid & 3) * 32;      // warp m offset in tile
    int wn = (wid >> 2) * 64;     // warp n offset in tile

    const __nv_bfloat16* Ah = g_Ah + (size_t)br * DD;
    const __nv_bfloat16* Al = g_Al + (size_t)br * DD;
    const __nv_bfloat16* Bh = g_Bh + (size_t)bc * DD;
    const __nv_bfloat16* Bl = g_Bl + (size_t)bc * DD;

    float acc[2][8][4];
#pragma unroll
    for (int i = 0; i < 2; i++)
#pragma unroll
        for (int j = 0; j < 8; j++)
#pragma unroll
            for (int q = 0; q < 4; q++) acc[i][j][q] = 0.0f;

    // ldmatrix lane address components
    const int a_row  = lane & 15;               // + wm + mt*16
    const int a_koff = (lane >> 4) * 16;        // bytes (8 bf16)
    const int b_nrow = (lane & 7) + ((lane >> 4) * 8);  // + wn + nt*16
    const int b_koff = ((lane >> 3) & 1) * 16;  // bytes

    load_chunk(base, Ah, Al, Bh, Bl, 0, t);
    asm volatile("cp.async.commit_group;");

    for (int c = 0; c < 8; c++) {
        uint32_t s = base + (uint32_t)(c & 1) * 65536u;
        if (c < 7) {
            uint32_t ns = base + (uint32_t)((c + 1) & 1) * 65536u;
            load_chunk(ns, Ah, Al, Bh, Bl, (c + 1) * 64, t);
            asm volatile("cp.async.commit_group;");
            asm volatile("cp.async.wait_group 1;");
        } else {
            asm volatile("cp.async.wait_group 0;");
        }
        __syncthreads();

#pragma unroll
        for (int ks = 0; ks < 4; ks++) {
            uint32_t ah[2][4], al[2][4], bh[4][4], bl[4][4];
#pragma unroll
            for (int mt = 0; mt < 2; mt++) {
                uint32_t off = (uint32_t)(wm + mt * 16 + a_row) * 128u
                             + (uint32_t)ks * 32u + (uint32_t)a_koff;
                uint32_t sw = off ^ ((off >> 3) & 0x70);
                ldsm_x4(ah[mt], s + sw);
                ldsm_x4(al[mt], s + 16384u + sw);
            }
#pragma unroll
            for (int nt = 0; nt < 4; nt++) {
                uint32_t off = (uint32_t)(wn + nt * 16 + b_nrow) * 128u
                             + (uint32_t)ks * 32u + (uint32_t)b_koff;
                uint32_t sw = off ^ ((off >> 3) & 0x70);
                ldsm_x4(bh[nt], s + 32768u + sw);
                ldsm_x4(bl[nt], s + 49152u + sw);
            }
#pragma unroll
            for (int mt = 0; mt < 2; mt++)
#pragma unroll
                for (int n8 = 0; n8 < 8; n8++) {
                    mma16816(acc[mt][n8], ah[mt], &bh[n8 >> 1][(n8 & 1) * 2]);
                    mma16816(acc[mt][n8], ah[mt], &bl[n8 >> 1][(n8 & 1) * 2]);
                    mma16816(acc[mt][n8], al[mt], &bh[n8 >> 1][(n8 & 1) * 2]);
                }
        }
        __syncthreads();   // protect buffer (c&1) before iter c+1 overwrites it
    }

    // epilogue: fragment (m16n8) thread map: row = t/4 (+8 for c[2],c[3]),
    // cols = 2*(t%4) + {0,1}
#pragma unroll
    for (int mt = 0; mt < 2; mt++) {
#pragma unroll
        for (int rg = 0; rg < 2; rg++) {
            int row = br + wm + mt * 16 + rg * 8 + (lane >> 2);
            float* dst = g_sim + (size_t)row * KC + bc + wn + (lane & 3) * 2;
#pragma unroll
            for (int n8 = 0; n8 < 8; n8++)
                *(float2*)(dst + n8 * 8) =
                    make_float2(acc[mt][n8][rg * 2], acc[mt][n8][rg * 2 + 1]);
        }
    }
}

// 16 rows/CTA: softmax stats, entropy (log-free per element + analytic eps
// correction), diversity, argmax candidate collection (rescued in fp32 later)
#define RPC 16
__global__ __launch_bounds__(256)
void row_kernel() {
    __shared__ float divp[KC];
    __shared__ int scount;
    int t = threadIdx.x;
    for (int i = t; i < KC; i += 256) divp[i] = 0.0f;

    float ent_acc = 0.0f;     // accumulated on t==0 only
    int r0 = blockIdx.x * RPC;
    for (int rr = 0; rr < RPC; rr++) {
        int r = r0 + rr;
        if (t == 0) scount = 0;
        __syncthreads();
        const float* srow = g_sim + (size_t)r * KC;
        float v[8];
#pragma unroll
        for (int j = 0; j < 8; j++) v[j] = srow[t + 256 * j];

        float m = v[0];
#pragma unroll
        for (int j = 1; j < 8; j++) m = fmaxf(m, v[j]);
        m = blockMax(m);

        float thr = m - MARGIN;
#pragma unroll
        for (int j = 0; j < 8; j++) {
            if (v[j] > thr) {
                int p = atomicAdd(&scount, 1);
                if (p < MAXCAND) g_cand[r][p] = t + 256 * j;
            }
        }

        float e[8], zp = 0.0f, evp = 0.0f;
#pragma unroll
        for (int j = 0; j < 8; j++) {
            e[j] = __expf(v[j] - m);
            zp += e[j];
            evp = fmaf(e[j], v[j], evp);
        }
        float z  = blockSum(zp);
        float ev = blockSum(evp);
        float invz = 1.0f / z;
#pragma unroll
        for (int j = 0; j < 8; j++) divp[t + 256 * j] += e[j] * invz;

        if (t == 0) {
            // sum_k p*log2(p+eps) = log2(e)*(E[v] - m) - log2(z) + K*eps*log2(e)
            ent_acc += 1.4426950408889634f * (ev * invz - m) - log2f(z) + EPS_CORR;
            g_ncand[r] = scount;
        }
    }
    if (t == 0) atomicAdd(&g_hsum, (double)ent_acc);
    __syncthreads();
    for (int i = t; i < KC; i += 256) atomicAdd(&g_div[i], divp[i]);
}

// exact fp32 rescue of argmax among candidates (one warp per row)
static __device__ __forceinline__ float dotrow(const float4 xv[4], const float* crow, int l) {
    const float4* c4 = (const float4*)crow;
    float s = 0.0f;
#pragma unroll
    for (int j = 0; j < 4; j++) {
        float4 c = c4[l + 32 * j];
        s = fmaf(xv[j].x, c.x, s);
        s = fmaf(xv[j].y, c.y, s);
        s = fmaf(xv[j].z, c.z, s);
        s = fmaf(xv[j].w, c.w, s);
    }
#pragma unroll
    for (int o = 16; o; o >>= 1) s += __shfl_xor_sync(0xffffffffu, s, o);
    return s;
}

__global__ __launch_bounds__(256)
void rescue_kernel(const float* __restrict__ x, const float* __restrict__ cb) {
    int w = (blockIdx.x * 256 + threadIdx.x) >> 5;   // row (grid exact)
    int l = threadIdx.x & 31;
    const float4* xr = (const float4*)(x + (size_t)w * DD);
    float4 xv[4];
#pragma unroll
    for (int j = 0; j < 4; j++) xv[j] = xr[l + 32 * j];

    int nc = g_ncand[w];
    float best = -3.4e38f;
    int bi = 0x7fffffff;
    if (nc <= MAXCAND) {
        for (int j = 0; j < nc; j++) {
            int col = g_cand[w][j];
            float d = dotrow(xv, cb + (size_t)col * DD, l);
            if (d > best || (d == best && col < bi)) { best = d; bi = col; }
        }
    } else {
        // overflow fallback: exact full scan (expected never)
        for (int col = 0; col < KC; col++) {
            float d = dotrow(xv, cb + (size_t)col * DD, l);
            if (d > best || (d == best && col < bi)) { best = d; bi = col; }
        }
    }
    if (l == 0) {
        g_idx[w] = bi;
        atomicAdd(&g_cnt[bi], 1.0f);
    }
}

__global__ __launch_bounds__(256)
void finalize_kernel(float invN) {
    int t = threadIdx.x;
    float local = 0.0f;
    for (int i = t; i < KC; i += 256) {
        float d = g_div[i] * invN;
        local += d * log2f(d + EPSQ);
    }
    float HD = blockSum(local);   // = -h_diversity
    if (t == 0) {
        float hclust = -(float)(g_hsum * (double)invN);
        g_loss = hclust + HD;     // h_clust - GAMMA*h_diversity, GAMMA=1
    }
}

// one warp per row: gather codebook row, center, L2-normalize, straight-through
__global__ __launch_bounds__(256)
void quant_kernel(const float* __restrict__ x, const float* __restrict__ cb,
                  float* __restrict__ oq, int nrows) {
    int w = (blockIdx.x * 256 + threadIdx.x) >> 5;
    if (w >= nrows) return;
    int l = threadIdx.x & 31;
    const float* crow = cb + (size_t)g_idx[w] * DD;
    const float* xrow = x + (size_t)w * DD;
    float4 q[4];
    float s = 0.0f;
#pragma unroll
    for (int j = 0; j < 4; j++) {
        q[j] = *(const float4*)(crow + j * 128 + l * 4);
        s += q[j].x + q[j].y + q[j].z + q[j].w;
    }
#pragma unroll
    for (int o = 16; o; o >>= 1) s += __shfl_xor_sync(0xffffffffu, s, o);
    float mean = s * (1.0f / (float)DD);
    float ss = 0.0f;
#pragma unroll
    for (int j = 0; j < 4; j++) {
        float dx = q[j].x - mean, dy = q[j].y - mean, dz = q[j].z - mean, dw = q[j].w - mean;
        ss += dx * dx + dy * dy + dz * dz + dw * dw;
    }
#pragma unroll
    for (int o = 16; o; o >>= 1) ss += __shfl_xor_sync(0xffffffffu, ss, o);
    float nrm = sqrtf(ss);
#pragma unroll
    for (int j = 0; j < 4; j++) {
        float4 xv = *(const float4*)(xrow + j * 128 + l * 4);
        float4 o4;
        o4.x = xv.x + ((q[j].x - mean) / nrm - xv.x);
        o4.y = xv.y + ((q[j].y - mean) / nrm - xv.y);
        o4.z = xv.z + ((q[j].z - mean) / nrm - xv.z);
        o4.w = xv.w + ((q[j].w - mean) / nrm - xv.w);
        *(float4*)(oq + (size_t)w * DD + j * 128 + l * 4) = o4;
    }
}

__global__ void fill_loss_kernel(float4* __restrict__ o, size_t n4) {
    float v = g_loss;
    float4 f = make_float4(v, v, v, v);
    size_t i = (size_t)blockIdx.x * blockDim.x + threadIdx.x;
    size_t stride = (size_t)gridDim.x * blockDim.x;
    for (; i < n4; i += stride) o[i] = f;
}

__global__ void misc_kernel(const float* __restrict__ cb,
                            const float* __restrict__ old_counts,
                            const int* __restrict__ train,
                            float* __restrict__ o_idx,
                            float* __restrict__ o_cb,
                            float* __restrict__ o_cnt, int nrows) {
    int gid = blockIdx.x * blockDim.x + threadIdx.x;
    if (gid < (KC * DD) / 4) ((float4*)o_cb)[gid] = ((const float4*)cb)[gid];
    if (gid < nrows) o_idx[gid] = (float)g_idx[gid];
    if (gid < KC) {
        float oldc = old_counts[gid];
        o_cnt[gid] = (*train) ? (0.99f * oldc + 0.01f * g_cnt[gid]) : oldc;
    }
}

// ---------------- launch ----------------------------------------------------
extern "C" void kernel_launch(void* const* d_in, const int* in_sizes, int n_in,
                              void* d_out, int out_size) {
    const float* inputs   = (const float*)d_in[0];
    const float* codebook = (const float*)d_in[1];
    const float* counts   = (const float*)d_in[2];
    const int*   train    = (const int*)d_in[3];

    const int nrows = in_sizes[0] / DD;     // 16384

    float* out    = (float*)d_out;
    float* o_q    = out;
    float* o_loss = o_q + (size_t)nrows * DD;
    float* o_idx  = o_loss + (size_t)nrows * KC;
    float* o_cb   = o_idx + nrows;
    float* o_cnt  = o_cb + (size_t)KC * DD;

    const int MM_SMEM = 131072 + 1024;
    cudaFuncSetAttribute(mm_kernel, cudaFuncAttributeMaxDynamicSharedMemorySize, MM_SMEM);

    init_kernel<<<(KC + 255) / 256, 256>>>();

    const int NA4 = NMAX * DD / 4, NB4 = KC * DD / 4;
    convert_kernel<<<(NA4 + NB4 + 255) / 256, 256>>>((const float4*)inputs,
                                                     (const float4*)codebook);

    dim3 gemm_grid(KC / 128, nrows / 128);
    mm_kernel<<<gemm_grid, 256, MM_SMEM>>>();

    row_kernel<<<nrows / RPC, 256>>>();

    rescue_kernel<<<nrows / 8, 256>>>(inputs, codebook);

    finalize_kernel<<<1, 256>>>(1.0f / (float)nrows);

    quant_kernel<<<(nrows + 7) / 8, 256>>>(inputs, codebook, o_q, nrows);

    size_t n4 = ((size_t)nrows * KC) / 4;
    fill_loss_kernel<<<2368, 256>>>((float4*)o_loss, n4);

    misc_kernel<<<(KC * DD / 4 + 255) / 256, 256>>>(codebook, counts, train,
                                                    o_idx, o_cb, o_cnt, nrows);
}

// round 12
// speedup vs baseline: 4.2757x; 1.7630x over previous
#include <cuda_runtime.h>
#include <cuda_bf16.h>
#include <math.h>
#include <stdint.h>

// Problem-instance constants (VectorQuantizerEnt: B=32,T=512,D=512,K=2048)
#define KC   2048
#define DD   512
#define NMAX 16384
#define EPSQ 1e-8f
#define MARGIN 0.01f
#define MAXCAND 16
// sum_k p*log2((p+eps)/p) ~= K*eps*log2(e)  (exact to ~3e-10 here since eps/p <= 1e-4)
#define EPS_CORR 2.9546194437325826e-5f

// ---------------- scratch (static device globals) ---------------------------
__device__ float         g_sim[(size_t)NMAX * KC];
__device__ __nv_bfloat16 g_Ah[(size_t)NMAX * DD];
__device__ __nv_bfloat16 g_Bh[(size_t)KC * DD];
__device__ float  g_div[KC];
__device__ float  g_cnt[KC];
__device__ int    g_idx[NMAX];
__device__ int    g_cand[NMAX][MAXCAND];
__device__ int    g_ncand[NMAX];
__device__ double g_hsum;
__device__ float  g_loss;

// ---------------- small PTX helpers -----------------------------------------
static __device__ __forceinline__ uint32_t smem_u32(const void* p) {
    uint32_t a;
    asm("{ .reg .u64 t; cvta.to.shared.u64 t, %1; cvt.u32.u64 %0, t; }" : "=r"(a) : "l"(p));
    return a;
}
static __device__ __forceinline__ void ldsm_x4(uint32_t* r, uint32_t addr) {
    asm volatile("ldmatrix.sync.aligned.m8n8.x4.shared.b16 {%0,%1,%2,%3}, [%4];"
                 : "=r"(r[0]), "=r"(r[1]), "=r"(r[2]), "=r"(r[3]) : "r"(addr));
}
static __device__ __forceinline__ void mma16816(float* c, const uint32_t* a, const uint32_t* b) {
    asm volatile("mma.sync.aligned.m16n8k16.row.col.f32.bf16.bf16.f32 "
                 "{%0,%1,%2,%3}, {%4,%5,%6,%7}, {%8,%9}, {%0,%1,%2,%3};"
                 : "+f"(c[0]), "+f"(c[1]), "+f"(c[2]), "+f"(c[3])
                 : "r"(a[0]), "r"(a[1]), "r"(a[2]), "r"(a[3]), "r"(b[0]), "r"(b[1]));
}

// ---------------- reductions ------------------------------------------------
__device__ __forceinline__ float blockSum(float v) {
    __shared__ float s[8];
    int t = threadIdx.x, w = t >> 5, l = t & 31;
#pragma unroll
    for (int o = 16; o; o >>= 1) v += __shfl_xor_sync(0xffffffffu, v, o);
    if (l == 0) s[w] = v;
    __syncthreads();
    if (w == 0) {
        float x = (l < 8) ? s[l] : 0.0f;
#pragma unroll
        for (int o = 4; o; o >>= 1) x += __shfl_xor_sync(0xffffffffu, x, o);
        if (l == 0) s[0] = x;
    }
    __syncthreads();
    float r = s[0];
    __syncthreads();
    return r;
}

// simultaneous block-sum of two floats (one barrier structure)
__device__ __forceinline__ float2 blockSum2(float a, float b) {
    __shared__ float2 s2[8];
    int t = threadIdx.x, w = t >> 5, l = t & 31;
#pragma unroll
    for (int o = 16; o; o >>= 1) {
        a += __shfl_xor_sync(0xffffffffu, a, o);
        b += __shfl_xor_sync(0xffffffffu, b, o);
    }
    if (l == 0) s2[w] = make_float2(a, b);
    __syncthreads();
    if (w == 0) {
        float x = (l < 8) ? s2[l].x : 0.0f;
        float y = (l < 8) ? s2[l].y : 0.0f;
#pragma unroll
        for (int o = 4; o; o >>= 1) {
            x += __shfl_xor_sync(0xffffffffu, x, o);
            y += __shfl_xor_sync(0xffffffffu, y, o);
        }
        if (l == 0) s2[0] = make_float2(x, y);
    }
    __syncthreads();
    float2 r = s2[0];
    __syncthreads();
    return r;
}

__device__ __forceinline__ float blockMax(float v) {
    __shared__ float s[8];
    int t = threadIdx.x, w = t >> 5, l = t & 31;
#pragma unroll
    for (int o = 16; o; o >>= 1) v = fmaxf(v, __shfl_xor_sync(0xffffffffu, v, o));
    if (l == 0) s[w] = v;
    __syncthreads();
    if (w == 0) {
        float x = (l < 8) ? s[l] : -3.4e38f;
#pragma unroll
        for (int o = 4; o; o >>= 1) x = fmaxf(x, __shfl_xor_sync(0xffffffffu, x, o));
        if (l == 0) s[0] = x;
    }
    __syncthreads();
    float r = s[0];
    __syncthreads();
    return r;
}

// ---------------- kernels ---------------------------------------------------
__global__ void init_kernel() {
    int gid = blockIdx.x * blockDim.x + threadIdx.x;
    if (gid < KC) { g_div[gid] = 0.0f; g_cnt[gid] = 0.0f; }
    if (gid == 0) g_hsum = 0.0;
}

// fp32 -> bf16 convert of inputs + codebook
__global__ void convert_kernel(const float4* __restrict__ A, const float4* __restrict__ B) {
    const int NA4 = NMAX * DD / 4;
    const int NB4 = KC * DD / 4;
    int i = blockIdx.x * 256 + threadIdx.x;
    const float4* src;
    __nv_bfloat162* oh;
    int j;
    if (i < NA4) {
        src = A; j = i; oh = (__nv_bfloat162*)g_Ah;
    } else if (i < NA4 + NB4) {
        src = B; j = i - NA4; oh = (__nv_bfloat162*)g_Bh;
    } else return;
    float4 f = src[j];
    oh[2 * j]     = __floats2bfloat162_rn(f.x, f.y);
    oh[2 * j + 1] = __floats2bfloat162_rn(f.z, f.w);
}

// cp.async one 128x64 bf16 chunk (16KB) each for A and B into SW128 SMEM
// stage layout: [A:0, B:16K], stage size 32KB
static __device__ __forceinline__ void load_chunk(
    uint32_t s,
    const __nv_bfloat16* __restrict__ Ah, const __nv_bfloat16* __restrict__ Bh,
    int k0, int t)
{
    const char* pA = (const char*)(Ah + k0);
    const char* pB = (const char*)(Bh + k0);
#pragma unroll
    for (int i = 0; i < 4; i++) {
        int u = t + i * 256;           // 1024 16B units: 128 rows x 8 units
        int row = u >> 3, c16 = u & 7;
        uint32_t off = (uint32_t)row * 128u + (uint32_t)c16 * 16u;
        uint32_t sw  = off ^ ((off >> 3) & 0x70);
        size_t go = (size_t)row * (DD * 2) + c16 * 16;
        asm volatile("cp.async.cg.shared.global [%0], [%1], 16;" :: "r"(s + sw),          "l"(pA + go));
        asm volatile("cp.async.cg.shared.global [%0], [%1], 16;" :: "r"(s + 16384u + sw), "l"(pB + go));
    }
}

// C = A_bf16 * B_bf16^T via mma.sync m16n8k16 (fp32 accum).
// 128x128 tile, BK=64, double-buffered cp.async, 8 warps (4m x 2n), warp=32x64.
// 2 CTAs/SM (64KB smem each) for latency hiding.
__global__ __launch_bounds__(256, 2) void mm_kernel() {
    extern __shared__ char dyn[];
    uint32_t raw  = smem_u32(dyn);
    uint32_t base = (raw + 1023u) & ~1023u;
    int t = threadIdx.x, wid = t >> 5, lane = t & 31;
    int bc = blockIdx.x * 128, br = blockIdx.y * 128;
    int wm = (wid & 3) * 32;      // warp m offset in tile
    int wn = (wid >> 2) * 64;     // warp n offset in tile

    const __nv_bfloat16* Ah = g_Ah + (size_t)br * DD;
    const __nv_bfloat16* Bh = g_Bh + (size_t)bc * DD;

    float acc[2][8][4];
#pragma unroll
    for (int i = 0; i < 2; i++)
#pragma unroll
        for (int j = 0; j < 8; j++)
#pragma unroll
            for (int q = 0; q < 4; q++) acc[i][j][q] = 0.0f;

    // ldmatrix lane address components
    const int a_row  = lane & 15;               // + wm + mt*16
    const int a_koff = (lane >> 4) * 16;        // bytes (8 bf16)
    const int b_nrow = (lane & 7) + ((lane >> 4) * 8);  // + wn + nt*16
    const int b_koff = ((lane >> 3) & 1) * 16;  // bytes

    load_chunk(base, Ah, Bh, 0, t);
    asm volatile("cp.async.commit_group;");

    for (int c = 0; c < 8; c++) {
        uint32_t s = base + (uint32_t)(c & 1) * 32768u;
        if (c < 7) {
            uint32_t ns = base + (uint32_t)((c + 1) & 1) * 32768u;
            load_chunk(ns, Ah, Bh, (c + 1) * 64, t);
            asm volatile("cp.async.commit_group;");
            asm volatile("cp.async.wait_group 1;");
        } else {
            asm volatile("cp.async.wait_group 0;");
        }
        __syncthreads();

#pragma unroll
        for (int ks = 0; ks < 4; ks++) {
            uint32_t ah[2][4], bh[4][4];
#pragma unroll
            for (int mt = 0; mt < 2; mt++) {
                uint32_t off = (uint32_t)(wm + mt * 16 + a_row) * 128u
                             + (uint32_t)ks * 32u + (uint32_t)a_koff;
                ldsm_x4(ah[mt], s + (off ^ ((off >> 3) & 0x70)));
            }
#pragma unroll
            for (int nt = 0; nt < 4; nt++) {
                uint32_t off = (uint32_t)(wn + nt * 16 + b_nrow) * 128u
                             + (uint32_t)ks * 32u + (uint32_t)b_koff;
                ldsm_x4(bh[nt], s + 16384u + (off ^ ((off >> 3) & 0x70)));
            }
#pragma unroll
            for (int mt = 0; mt < 2; mt++)
#pragma unroll
                for (int n8 = 0; n8 < 8; n8++)
                    mma16816(acc[mt][n8], ah[mt], &bh[n8 >> 1][(n8 & 1) * 2]);
        }
        __syncthreads();   // protect buffer (c&1) before iter c+1 overwrites it
    }

    // epilogue: fragment (m16n8) thread map: row = t/4 (+8 for c[2],c[3]),
    // cols = 2*(t%4) + {0,1}
#pragma unroll
    for (int mt = 0; mt < 2; mt++) {
#pragma unroll
        for (int rg = 0; rg < 2; rg++) {
            int row = br + wm + mt * 16 + rg * 8 + (lane >> 2);
            float* dst = g_sim + (size_t)row * KC + bc + wn + (lane & 3) * 2;
#pragma unroll
            for (int n8 = 0; n8 < 8; n8++)
                *(float2*)(dst + n8 * 8) =
                    make_float2(acc[mt][n8][rg * 2], acc[mt][n8][rg * 2 + 1]);
        }
    }
}

// 16 rows/CTA: softmax stats, entropy (log-free per element + analytic eps
// correction), diversity, argmax candidate collection (rescued in fp32 later)
#define RPC 16
__global__ __launch_bounds__(256)
void row_kernel() {
    __shared__ float divp[KC];
    __shared__ int scount;
    int t = threadIdx.x;
    for (int i = t; i < KC; i += 256) divp[i] = 0.0f;

    float ent_acc = 0.0f;     // accumulated on t==0 only
    int r0 = blockIdx.x * RPC;
    for (int rr = 0; rr < RPC; rr++) {
        int r = r0 + rr;
        if (t == 0) scount = 0;
        __syncthreads();
        const float* srow = g_sim + (size_t)r * KC;
        float v[8];
#pragma unroll
        for (int j = 0; j < 8; j++) v[j] = srow[t + 256 * j];

        float m = v[0];
#pragma unroll
        for (int j = 1; j < 8; j++) m = fmaxf(m, v[j]);
        m = blockMax(m);

        float thr = m - MARGIN;
#pragma unroll
        for (int j = 0; j < 8; j++) {
            if (v[j] > thr) {
                int p = atomicAdd(&scount, 1);
                if (p < MAXCAND) g_cand[r][p] = t + 256 * j;
            }
        }

        float e[8], zp = 0.0f, evp = 0.0f;
#pragma unroll
        for (int j = 0; j < 8; j++) {
            e[j] = __expf(v[j] - m);
            zp += e[j];
            evp = fmaf(e[j], v[j], evp);
        }
        float2 ze = blockSum2(zp, evp);
        float z = ze.x, ev = ze.y;
        float invz = 1.0f / z;
#pragma unroll
        for (int j = 0; j < 8; j++) divp[t + 256 * j] += e[j] * invz;

        if (t == 0) {
            // sum_k p*log2(p+eps) = log2(e)*(E[v] - m) - log2(z) + K*eps*log2(e)
            ent_acc += 1.4426950408889634f * (ev * invz - m) - log2f(z) + EPS_CORR;
            g_ncand[r] = scount;
        }
    }
    if (t == 0) atomicAdd(&g_hsum, (double)ent_acc);
    __syncthreads();
    for (int i = t; i < KC; i += 256) atomicAdd(&g_div[i], divp[i]);
}

// exact fp32 rescue of argmax among candidates (one warp per row)
static __device__ __forceinline__ float dotrow(const float4 xv[4], const float* crow, int l) {
    const float4* c4 = (const float4*)crow;
    float s = 0.0f;
#pragma unroll
    for (int j = 0; j < 4; j++) {
        float4 c = c4[l + 32 * j];
        s = fmaf(xv[j].x, c.x, s);
        s = fmaf(xv[j].y, c.y, s);
        s = fmaf(xv[j].z, c.z, s);
        s = fmaf(xv[j].w, c.w, s);
    }
#pragma unroll
    for (int o = 16; o; o >>= 1) s += __shfl_xor_sync(0xffffffffu, s, o);
    return s;
}

__global__ __launch_bounds__(256)
void rescue_kernel(const float* __restrict__ x, const float* __restrict__ cb) {
    int w = (blockIdx.x * 256 + threadIdx.x) >> 5;   // row (grid exact)
    int l = threadIdx.x & 31;
    const float4* xr = (const float4*)(x + (size_t)w * DD);
    float4 xv[4];
#pragma unroll
    for (int j = 0; j < 4; j++) xv[j] = xr[l + 32 * j];

    int nc = g_ncand[w];
    float best = -3.4e38f;
    int bi = 0x7fffffff;
    if (nc <= MAXCAND) {
        for (int j = 0; j < nc; j++) {
            int col = g_cand[w][j];
            float d = dotrow(xv, cb + (size_t)col * DD, l);
            if (d > best || (d == best && col < bi)) { best = d; bi = col; }
        }
    } else {
        // overflow fallback: exact full scan (expected never)
        for (int col = 0; col < KC; col++) {
            float d = dotrow(xv, cb + (size_t)col * DD, l);
            if (d > best || (d == best && col < bi)) { best = d; bi = col; }
        }
    }
    if (l == 0) {
        g_idx[w] = bi;
        atomicAdd(&g_cnt[bi], 1.0f);
    }
}

__global__ __launch_bounds__(256)
void finalize_kernel(float invN) {
    int t = threadIdx.x;
    float local = 0.0f;
    for (int i = t; i < KC; i += 256) {
        float d = g_div[i] * invN;
        local += d * log2f(d + EPSQ);
    }
    float HD = blockSum(local);   // = -h_diversity
    if (t == 0) {
        float hclust = -(float)(g_hsum * (double)invN);
        g_loss = hclust + HD;     // h_clust - GAMMA*h_diversity, GAMMA=1
    }
}

// one warp per row: gather codebook row, center, L2-normalize, straight-through
__global__ __launch_bounds__(256)
void quant_kernel(const float* __restrict__ x, const float* __restrict__ cb,
                  float* __restrict__ oq, int nrows) {
    int w = (blockIdx.x * 256 + threadIdx.x) >> 5;
    if (w >= nrows) return;
    int l = threadIdx.x & 31;
    const float* crow = cb + (size_t)g_idx[w] * DD;
    const float* xrow = x + (size_t)w * DD;
    float4 q[4];
    float s = 0.0f;
#pragma unroll
    for (int j = 0; j < 4; j++) {
        q[j] = *(const float4*)(crow + j * 128 + l * 4);
        s += q[j].x + q[j].y + q[j].z + q[j].w;
    }
#pragma unroll
    for (int o = 16; o; o >>= 1) s += __shfl_xor_sync(0xffffffffu, s, o);
    float mean = s * (1.0f / (float)DD);
    float ss = 0.0f;
#pragma unroll
    for (int j = 0; j < 4; j++) {
        float dx = q[j].x - mean, dy = q[j].y - mean, dz = q[j].z - mean, dw = q[j].w - mean;
        ss += dx * dx + dy * dy + dz * dz + dw * dw;
    }
#pragma unroll
    for (int o = 16; o; o >>= 1) ss += __shfl_xor_sync(0xffffffffu, ss, o);
    float nrm = sqrtf(ss);
#pragma unroll
    for (int j = 0; j < 4; j++) {
        float4 xv = *(const float4*)(xrow + j * 128 + l * 4);
        float4 o4;
        o4.x = xv.x + ((q[j].x - mean) / nrm - xv.x);
        o4.y = xv.y + ((q[j].y - mean) / nrm - xv.y);
        o4.z = xv.z + ((q[j].z - mean) / nrm - xv.z);
        o4.w = xv.w + ((q[j].w - mean) / nrm - xv.w);
        *(float4*)(oq + (size_t)w * DD + j * 128 + l * 4) = o4;
    }
}

__global__ void fill_loss_kernel(float4* __restrict__ o, size_t n4) {
    float v = g_loss;
    float4 f = make_float4(v, v, v, v);
    size_t i = (size_t)blockIdx.x * blockDim.x + threadIdx.x;
    size_t stride = (size_t)gridDim.x * blockDim.x;
    for (; i < n4; i += stride) o[i] = f;
}

__global__ void misc_kernel(const float* __restrict__ cb,
                            const float* __restrict__ old_counts,
                            const int* __restrict__ train,
                            float* __restrict__ o_idx,
                            float* __restrict__ o_cb,
                            float* __restrict__ o_cnt, int nrows) {
    int gid = blockIdx.x * blockDim.x + threadIdx.x;
    if (gid < (KC * DD) / 4) ((float4*)o_cb)[gid] = ((const float4*)cb)[gid];
    if (gid < nrows) o_idx[gid] = (float)g_idx[gid];
    if (gid < KC) {
        float oldc = old_counts[gid];
        o_cnt[gid] = (*train) ? (0.99f * oldc + 0.01f * g_cnt[gid]) : oldc;
    }
}

// ---------------- launch ----------------------------------------------------
extern "C" void kernel_launch(void* const* d_in, const int* in_sizes, int n_in,
                              void* d_out, int out_size) {
    const float* inputs   = (const float*)d_in[0];
    const float* codebook = (const float*)d_in[1];
    const float* counts   = (const float*)d_in[2];
    const int*   train    = (const int*)d_in[3];

    const int nrows = in_sizes[0] / DD;     // 16384

    float* out    = (float*)d_out;
    float* o_q    = out;
    float* o_loss = o_q + (size_t)nrows * DD;
    float* o_idx  = o_loss + (size_t)nrows * KC;
    float* o_cb   = o_idx + nrows;
    float* o_cnt  = o_cb + (size_t)KC * DD;

    const int MM_SMEM = 65536 + 1024;
    cudaFuncSetAttribute(mm_kernel, cudaFuncAttributeMaxDynamicSharedMemorySize, MM_SMEM);

    init_kernel<<<(KC + 255) / 256, 256>>>();

    const int NA4 = NMAX * DD / 4, NB4 = KC * DD / 4;
    convert_kernel<<<(NA4 + NB4 + 255) / 256, 256>>>((const float4*)inputs,
                                                     (const float4*)codebook);

    dim3 gemm_grid(KC / 128, nrows / 128);
    mm_kernel<<<gemm_grid, 256, MM_SMEM>>>();

    row_kernel<<<nrows / RPC, 256>>>();

    rescue_kernel<<<nrows / 8, 256>>>(inputs, codebook);

    finalize_kernel<<<1, 256>>>(1.0f / (float)nrows);

    quant_kernel<<<(nrows + 7) / 8, 256>>>(inputs, codebook, o_q, nrows);

    size_t n4 = ((size_t)nrows * KC) / 4;
    fill_loss_kernel<<<2368, 256>>>((float4*)o_loss, n4);

    misc_kernel<<<(KC * DD / 4 + 255) / 256, 256>>>(codebook, counts, train,
                                                    o_idx, o_cb, o_cnt, nrows);
}